// round 4
// baseline (speedup 1.0000x reference)
#include <cuda_runtime.h>
#include <math.h>
#include <stdint.h>

#define EMB   1024
#define DK    64
#define BATCH 4
#define SEQ   4096
#define MROWS (BATCH * SEQ)   // 16384

// ---------------- scratch (allocation-free) ----------------
__device__ float g_q[MROWS * DK];   // [row][d]
__device__ float g_k[MROWS * DK];   // [row][d]
__device__ float g_v[MROWS * DK];   // [row][d]

// ---------------- helpers ----------------
__device__ __forceinline__ uint32_t f2tf(float f) {
    uint32_t u;
    asm("cvt.rna.tf32.f32 %0, %1;" : "=r"(u) : "f"(f));
    return u;
}
__device__ __forceinline__ float f2tff(float f) {
    return __uint_as_float(f2tf(f));
}

// D = A(16x8, row) * B(8x8, col) + D, tf32 inputs, f32 accum
__device__ __forceinline__ void mma8(float* c, const uint32_t* a,
                                     uint32_t b0, uint32_t b1) {
    asm volatile(
        "mma.sync.aligned.m16n8k8.row.col.f32.tf32.tf32.f32 "
        "{%0,%1,%2,%3}, {%4,%5,%6,%7}, {%8,%9}, {%0,%1,%2,%3};"
        : "+f"(c[0]), "+f"(c[1]), "+f"(c[2]), "+f"(c[3])
        : "r"(a[0]), "r"(a[1]), "r"(a[2]), "r"(a[3]), "r"(b0), "r"(b1));
}

// ============================================================
// Projection GEMM: C[16384,64] = X[16384,1024] @ W[1024,64] + b
// BM=128, BN=64, BK=32, 8 warps, prefetch double-buffered regs.
// ============================================================
#define XS_P 36   // floats per row; A-frag LDS.32 conflict-free
#define WS_PD 68  // dwords(8B) per row-pair of Ws2; 2-way max

__global__ __launch_bounds__(256) void proj_mma(
    const float* __restrict__ in1, const float* __restrict__ in2,
    const float* __restrict__ Wq, const float* __restrict__ bq,
    const float* __restrict__ Wk, const float* __restrict__ bk,
    const float* __restrict__ Wv, const float* __restrict__ bv)
{
    __shared__ float Xs[128][XS_P];
    __shared__ float Ws2[16 * WS_PD * 2];   // pairs (r, r+4) interleaved

    const int which = blockIdx.z;
    const float* X    = (which == 0) ? in2 : in1;
    const float* W    = (which == 0) ? Wq : (which == 1 ? Wk : Wv);
    const float* bias = (which == 0) ? bq : (which == 1 ? bk : bv);
    float* dst        = (which == 0) ? g_q : (which == 1 ? g_k : g_v);

    const int m0   = blockIdx.x * 128;
    const int tid  = threadIdx.x;
    const int warp = tid >> 5;
    const int lane = tid & 31;
    const int g    = lane >> 2;
    const int t4   = lane & 3;
    const int wm   = warp * 16;

    float acc[8][4];
    #pragma unroll
    for (int nt = 0; nt < 8; nt++)
        #pragma unroll
        for (int j = 0; j < 4; j++) acc[nt][j] = 0.f;

    float4 xpre[4], wpre[2];

    // ---- prologue: load tile 0 ----
    #pragma unroll
    for (int it = 0; it < 4; it++) {
        int idx = tid + it * 256;
        int r = idx >> 3, c4 = (idx & 7) * 4;
        xpre[it] = *(const float4*)(X + (size_t)(m0 + r) * EMB + c4);
    }
    #pragma unroll
    for (int it = 0; it < 2; it++) {
        int idx = tid + it * 256;
        int r = idx >> 4, c4 = (idx & 15) * 4;
        wpre[it] = *(const float4*)(W + (size_t)r * DK + c4);
    }

    for (int kt = 0; kt < EMB; kt += 32) {
        // ---- store prefetched tile to smem (tf32-rounded) ----
        #pragma unroll
        for (int it = 0; it < 4; it++) {
            int idx = tid + it * 256;
            int r = idx >> 3, c4 = (idx & 7) * 4;
            Xs[r][c4 + 0] = f2tff(xpre[it].x);
            Xs[r][c4 + 1] = f2tff(xpre[it].y);
            Xs[r][c4 + 2] = f2tff(xpre[it].z);
            Xs[r][c4 + 3] = f2tff(xpre[it].w);
        }
        #pragma unroll
        for (int it = 0; it < 2; it++) {
            int idx = tid + it * 256;
            int r = idx >> 4, c4 = (idx & 15) * 4;
            // pair slot: (ks = r>>3, t = r&3), half = (r&4)>>2
            int base = ((r >> 3) * 4 + (r & 3)) * WS_PD + c4;
            int half = (r >> 2) & 1;
            float* p = &Ws2[base * 2 + half];
            p[0] = f2tff(wpre[it].x);
            p[2] = f2tff(wpre[it].y);
            p[4] = f2tff(wpre[it].z);
            p[6] = f2tff(wpre[it].w);
        }
        __syncthreads();

        // ---- prefetch next tile ----
        if (kt + 32 < EMB) {
            #pragma unroll
            for (int it = 0; it < 4; it++) {
                int idx = tid + it * 256;
                int r = idx >> 3, c4 = (idx & 7) * 4;
                xpre[it] = *(const float4*)(X + (size_t)(m0 + r) * EMB + kt + 32 + c4);
            }
            #pragma unroll
            for (int it = 0; it < 2; it++) {
                int idx = tid + it * 256;
                int r = idx >> 4, c4 = (idx & 15) * 4;
                wpre[it] = *(const float4*)(W + (size_t)(kt + 32 + r) * DK + c4);
            }
        }

        // ---- compute ----
        #pragma unroll
        for (int ks = 0; ks < 4; ks++) {
            uint32_t a[4];
            a[0] = __float_as_uint(Xs[wm + g    ][ks * 8 + t4    ]);
            a[1] = __float_as_uint(Xs[wm + g + 8][ks * 8 + t4    ]);
            a[2] = __float_as_uint(Xs[wm + g    ][ks * 8 + t4 + 4]);
            a[3] = __float_as_uint(Xs[wm + g + 8][ks * 8 + t4 + 4]);
            #pragma unroll
            for (int nt = 0; nt < 8; nt++) {
                float2 wp = *(const float2*)&Ws2[((ks * 4 + t4) * WS_PD + nt * 8 + g) * 2];
                mma8(acc[nt], a, __float_as_uint(wp.x), __float_as_uint(wp.y));
            }
        }
        __syncthreads();
    }

    #pragma unroll
    for (int nt = 0; nt < 8; nt++) {
        const int col = nt * 8 + 2 * t4;
        const float b0 = bias[col], b1 = bias[col + 1];
        const int rowA = m0 + wm + g, rowB = rowA + 8;
        float2 oa = {acc[nt][0] + b0, acc[nt][1] + b1};
        float2 ob = {acc[nt][2] + b0, acc[nt][3] + b1};
        *(float2*)(dst + (size_t)rowA * DK + col) = oa;
        *(float2*)(dst + (size_t)rowB * DK + col) = ob;
    }
}

// ============================================================
// Flash attention, tf32 mma.sync, paired-fragment smem layouts,
// register-prefetch double buffering.
// CTA: 256 thr (8 warps x 16 q-rows = 128 q). KV tiles of 64.
// ============================================================
#define KS_PD 36   // dwords per key row of Ks2
#define VS_PD 68   // dwords per row-pair of Vs2
#define PS_P  68   // floats per row of Ps

#define KS2_OFF 0                         // 64*36*2 = 4608 floats
#define VS2_OFF (64 * KS_PD * 2)          // 4608
#define PS_OFF  (VS2_OFF + 32 * VS_PD * 2) // 4608+4352 = 8960
#define SM_FLOATS (PS_OFF + 128 * PS_P)   // 17664
#define SM_BYTES (SM_FLOATS * 4)          // 70656

__global__ __launch_bounds__(256) void flash_mma(float* __restrict__ out)
{
    extern __shared__ float sm[];
    float* KsF = sm + KS2_OFF;
    float* VsF = sm + VS2_OFF;
    float* Ps  = sm + PS_OFF;

    const int tid  = threadIdx.x;
    const int warp = tid >> 5;
    const int lane = tid & 31;
    const int g    = lane >> 2;
    const int t4   = lane & 3;
    const int wm   = warp * 16;
    const int b    = blockIdx.y;
    const int q0   = blockIdx.x * 128;

    // ---- Q fragments in registers (pre-scaled, tf32) ----
    uint32_t q[32];
    {
        const float* Qg = g_q + (size_t)(b * SEQ + q0 + wm) * DK;
        #pragma unroll
        for (int ks = 0; ks < 8; ks++) {
            q[ks * 4 + 0] = f2tf(0.125f * Qg[(size_t)(g    ) * DK + ks * 8 + t4    ]);
            q[ks * 4 + 1] = f2tf(0.125f * Qg[(size_t)(g + 8) * DK + ks * 8 + t4    ]);
            q[ks * 4 + 2] = f2tf(0.125f * Qg[(size_t)(g    ) * DK + ks * 8 + t4 + 4]);
            q[ks * 4 + 3] = f2tf(0.125f * Qg[(size_t)(g + 8) * DK + ks * 8 + t4 + 4]);
        }
    }

    float o[8][4];
    #pragma unroll
    for (int nt = 0; nt < 8; nt++)
        #pragma unroll
        for (int j = 0; j < 4; j++) o[nt][j] = 0.f;
    float mA = -INFINITY, mB = -INFINITY, lA = 0.f, lB = 0.f;

    const float* Kg0 = g_k + (size_t)(b * SEQ) * DK;
    const float* Vg0 = g_v + (size_t)(b * SEQ) * DK;

    float4 kpre[4], vpre[4];
    // ---- prologue: prefetch tile 0 ----
    #pragma unroll
    for (int it = 0; it < 4; it++) {
        int idx = tid + it * 256;
        int r = idx >> 4, c4 = (idx & 15) * 4;
        kpre[it] = *(const float4*)(Kg0 + (size_t)r * DK + c4);
        vpre[it] = *(const float4*)(Vg0 + (size_t)r * DK + c4);
    }

    for (int kt = 0; kt < SEQ; kt += 64) {
        // ---- store prefetched K/V to paired smem layouts ----
        #pragma unroll
        for (int it = 0; it < 4; it++) {
            int idx = tid + it * 256;
            int r = idx >> 4, c4 = (idx & 15) * 4;
            // K pairs: (d, d+4) within a key row; d = c4 + j all share half
            {
                int base = r * KS_PD + (c4 >> 3) * 4;      // dwords
                int half = (c4 >> 2) & 1;
                float* p = &KsF[base * 2 + half];
                p[0] = f2tff(kpre[it].x);
                p[2] = f2tff(kpre[it].y);
                p[4] = f2tff(kpre[it].z);
                p[6] = f2tff(kpre[it].w);
            }
            // V pairs: rows (r, r+4), same d column
            {
                int base = ((r >> 3) * 4 + (r & 3)) * VS_PD + c4;
                int half = (r >> 2) & 1;
                float* p = &VsF[base * 2 + half];
                p[0] = f2tff(vpre[it].x);
                p[2] = f2tff(vpre[it].y);
                p[4] = f2tff(vpre[it].z);
                p[6] = f2tff(vpre[it].w);
            }
        }
        __syncthreads();

        // ---- prefetch next tile ----
        if (kt + 64 < SEQ) {
            const float* Kg = Kg0 + (size_t)(kt + 64) * DK;
            const float* Vg = Vg0 + (size_t)(kt + 64) * DK;
            #pragma unroll
            for (int it = 0; it < 4; it++) {
                int idx = tid + it * 256;
                int r = idx >> 4, c4 = (idx & 15) * 4;
                kpre[it] = *(const float4*)(Kg + (size_t)r * DK + c4);
                vpre[it] = *(const float4*)(Vg + (size_t)r * DK + c4);
            }
        }

        // ---- S = Q @ K^T ----
        float s[8][4];
        #pragma unroll
        for (int nt = 0; nt < 8; nt++)
            #pragma unroll
            for (int j = 0; j < 4; j++) s[nt][j] = 0.f;

        #pragma unroll
        for (int ks = 0; ks < 8; ks++) {
            #pragma unroll
            for (int nt = 0; nt < 8; nt++) {
                float2 kp = *(const float2*)&KsF[((nt * 8 + g) * KS_PD + ks * 4 + t4) * 2];
                mma8(s[nt], &q[ks * 4], __float_as_uint(kp.x), __float_as_uint(kp.y));
            }
        }

        // ---- online softmax ----
        float mxA = -INFINITY, mxB = -INFINITY;
        #pragma unroll
        for (int nt = 0; nt < 8; nt++) {
            mxA = fmaxf(mxA, fmaxf(s[nt][0], s[nt][1]));
            mxB = fmaxf(mxB, fmaxf(s[nt][2], s[nt][3]));
        }
        mxA = fmaxf(mxA, __shfl_xor_sync(0xffffffffu, mxA, 1));
        mxA = fmaxf(mxA, __shfl_xor_sync(0xffffffffu, mxA, 2));
        mxB = fmaxf(mxB, __shfl_xor_sync(0xffffffffu, mxB, 1));
        mxB = fmaxf(mxB, __shfl_xor_sync(0xffffffffu, mxB, 2));

        const float mnA = fmaxf(mA, mxA), mnB = fmaxf(mB, mxB);
        const float cA = __expf(mA - mnA), cB = __expf(mB - mnB);

        float sumA = 0.f, sumB = 0.f;
        #pragma unroll
        for (int nt = 0; nt < 8; nt++) {
            s[nt][0] = __expf(s[nt][0] - mnA);
            s[nt][1] = __expf(s[nt][1] - mnA);
            s[nt][2] = __expf(s[nt][2] - mnB);
            s[nt][3] = __expf(s[nt][3] - mnB);
            sumA += s[nt][0] + s[nt][1];
            sumB += s[nt][2] + s[nt][3];
        }
        sumA += __shfl_xor_sync(0xffffffffu, sumA, 1);
        sumA += __shfl_xor_sync(0xffffffffu, sumA, 2);
        sumB += __shfl_xor_sync(0xffffffffu, sumB, 1);
        sumB += __shfl_xor_sync(0xffffffffu, sumB, 2);
        lA = lA * cA + sumA;  mA = mnA;
        lB = lB * cB + sumB;  mB = mnB;

        #pragma unroll
        for (int nt = 0; nt < 8; nt++) {
            o[nt][0] *= cA; o[nt][1] *= cA;
            o[nt][2] *= cB; o[nt][3] *= cB;
        }

        // ---- P -> warp-private smem (tf32) ----
        #pragma unroll
        for (int nt = 0; nt < 8; nt++) {
            const int col = nt * 8 + 2 * t4;
            uint2 pa = {f2tf(s[nt][0]), f2tf(s[nt][1])};
            uint2 pb = {f2tf(s[nt][2]), f2tf(s[nt][3])};
            *(uint2*)(Ps + (wm + g    ) * PS_P + col) = pa;
            *(uint2*)(Ps + (wm + g + 8) * PS_P + col) = pb;
        }
        __syncwarp();

        // ---- O += P @ V ----
        #pragma unroll
        for (int ks = 0; ks < 8; ks++) {
            uint32_t a[4];
            a[0] = __float_as_uint(Ps[(wm + g    ) * PS_P + ks * 8 + t4    ]);
            a[1] = __float_as_uint(Ps[(wm + g + 8) * PS_P + ks * 8 + t4    ]);
            a[2] = __float_as_uint(Ps[(wm + g    ) * PS_P + ks * 8 + t4 + 4]);
            a[3] = __float_as_uint(Ps[(wm + g + 8) * PS_P + ks * 8 + t4 + 4]);
            #pragma unroll
            for (int nt = 0; nt < 8; nt++) {
                float2 vp = *(const float2*)&VsF[((ks * 4 + t4) * VS_PD + nt * 8 + g) * 2];
                mma8(o[nt], a, __float_as_uint(vp.x), __float_as_uint(vp.y));
            }
        }
        __syncthreads();
    }

    // ---- epilogue ----
    const float ilA = 1.f / lA, ilB = 1.f / lB;
    const int rowA = b * SEQ + q0 + wm + g;
    const int rowB = rowA + 8;
    #pragma unroll
    for (int nt = 0; nt < 8; nt++) {
        const int col = nt * 8 + 2 * t4;
        float2 oa = {o[nt][0] * ilA, o[nt][1] * ilA};
        float2 ob = {o[nt][2] * ilB, o[nt][3] * ilB};
        *(float2*)(out + (size_t)rowA * DK + col) = oa;
        *(float2*)(out + (size_t)rowB * DK + col) = ob;
    }
}

// ---------------- launch ----------------
extern "C" void kernel_launch(void* const* d_in, const int* in_sizes, int n_in,
                              void* d_out, int out_size)
{
    const float* input1 = (const float*)d_in[0];
    const float* input2 = (const float*)d_in[1];
    const float* Wq = (const float*)d_in[2];
    const float* bq = (const float*)d_in[3];
    const float* Wk = (const float*)d_in[4];
    const float* bk = (const float*)d_in[5];
    const float* Wv = (const float*)d_in[6];
    const float* bv = (const float*)d_in[7];
    float* out = (float*)d_out;

    (void)in_sizes; (void)n_in; (void)out_size;

    dim3 pgrid(MROWS / 128, 1, 3);
    proj_mma<<<pgrid, 256>>>(input1, input2, Wq, bq, Wk, bk, Wv, bv);

    cudaFuncSetAttribute(flash_mma, cudaFuncAttributeMaxDynamicSharedMemorySize, SM_BYTES);
    dim3 fgrid(SEQ / 128, BATCH);
    flash_mma<<<fgrid, 256, SM_BYTES>>>(out);
}

// round 6
// speedup vs baseline: 1.6370x; 1.6370x over previous
#include <cuda_runtime.h>
#include <cuda_fp16.h>
#include <math.h>
#include <stdint.h>

#define EMB   1024
#define DK    64
#define BATCH 4
#define SEQ   4096
#define MROWS (BATCH * SEQ)   // 16384

// ---------------- scratch (allocation-free) ----------------
__device__ __align__(128) __half g_q[MROWS * DK];   // [row][d], pre-scaled by 1/8
__device__ __align__(128) __half g_k[MROWS * DK];   // [row][d]
__device__ __align__(128) __half g_vt[DK * MROWS];  // [d][row]  (transposed V)

// ---------------- helpers ----------------
__device__ __forceinline__ uint32_t f2tf(float f) {
    uint32_t u;
    asm("cvt.rna.tf32.f32 %0, %1;" : "=r"(u) : "f"(f));
    return u;
}
__device__ __forceinline__ uint32_t packh2(float x, float y) {
    uint32_t r;
    asm("cvt.rn.f16x2.f32 %0, %1, %2;" : "=r"(r) : "f"(y), "f"(x));
    return r;
}

// tf32: D(16x8) += A(16x8) * B(8x8)
__device__ __forceinline__ void mma8(float* c, const uint32_t* a,
                                     uint32_t b0, uint32_t b1) {
    asm volatile(
        "mma.sync.aligned.m16n8k8.row.col.f32.tf32.tf32.f32 "
        "{%0,%1,%2,%3}, {%4,%5,%6,%7}, {%8,%9}, {%0,%1,%2,%3};"
        : "+f"(c[0]), "+f"(c[1]), "+f"(c[2]), "+f"(c[3])
        : "r"(a[0]), "r"(a[1]), "r"(a[2]), "r"(a[3]), "r"(b0), "r"(b1));
}
// fp16: D(16x8) += A(16x16) * B(16x8), fp32 accum
__device__ __forceinline__ void mma16(float* c, const uint32_t* a,
                                      uint32_t b0, uint32_t b1) {
    asm volatile(
        "mma.sync.aligned.m16n8k16.row.col.f32.f16.f16.f32 "
        "{%0,%1,%2,%3}, {%4,%5,%6,%7}, {%8,%9}, {%0,%1,%2,%3};"
        : "+f"(c[0]), "+f"(c[1]), "+f"(c[2]), "+f"(c[3])
        : "r"(a[0]), "r"(a[1]), "r"(a[2]), "r"(a[3]), "r"(b0), "r"(b1));
}

// ============================================================
// Projection GEMM (tf32 mma): C[16384,64] = X @ W + b -> fp16 outputs
// BM=128, BN=64, BK=32, 8 warps.  (Round-3 structure.)
// ============================================================
#define XS_P 36
#define WS_P 72

__global__ __launch_bounds__(256) void proj_mma(
    const float* __restrict__ in1, const float* __restrict__ in2,
    const float* __restrict__ Wq, const float* __restrict__ bq,
    const float* __restrict__ Wk, const float* __restrict__ bk,
    const float* __restrict__ Wv, const float* __restrict__ bv)
{
    __shared__ float Xs[128][XS_P];
    __shared__ float Ws[32][WS_P];

    const int which = blockIdx.z;
    const float* X    = (which == 0) ? in2 : in1;
    const float* W    = (which == 0) ? Wq : (which == 1 ? Wk : Wv);
    const float* bias = (which == 0) ? bq : (which == 1 ? bk : bv);

    const int m0   = blockIdx.x * 128;
    const int tid  = threadIdx.x;
    const int warp = tid >> 5;
    const int lane = tid & 31;
    const int g    = lane >> 2;
    const int t4   = lane & 3;
    const int wm   = warp * 16;

    float acc[8][4];
    #pragma unroll
    for (int nt = 0; nt < 8; nt++)
        #pragma unroll
        for (int j = 0; j < 4; j++) acc[nt][j] = 0.f;

    for (int kt = 0; kt < EMB; kt += 32) {
        #pragma unroll
        for (int it = 0; it < 4; it++) {
            int idx = tid + it * 256;
            int r = idx >> 3, c4 = (idx & 7) * 4;
            float4 v = *(const float4*)(X + (size_t)(m0 + r) * EMB + kt + c4);
            Xs[r][c4 + 0] = __uint_as_float(f2tf(v.x));
            Xs[r][c4 + 1] = __uint_as_float(f2tf(v.y));
            Xs[r][c4 + 2] = __uint_as_float(f2tf(v.z));
            Xs[r][c4 + 3] = __uint_as_float(f2tf(v.w));
        }
        #pragma unroll
        for (int it = 0; it < 2; it++) {
            int idx = tid + it * 256;
            int r = idx >> 4, c4 = (idx & 15) * 4;
            float4 v = *(const float4*)(W + (size_t)(kt + r) * DK + c4);
            Ws[r][c4 + 0] = __uint_as_float(f2tf(v.x));
            Ws[r][c4 + 1] = __uint_as_float(f2tf(v.y));
            Ws[r][c4 + 2] = __uint_as_float(f2tf(v.z));
            Ws[r][c4 + 3] = __uint_as_float(f2tf(v.w));
        }
        __syncthreads();

        #pragma unroll
        for (int ks = 0; ks < 4; ks++) {
            uint32_t a[4];
            a[0] = __float_as_uint(Xs[wm + g    ][ks * 8 + t4    ]);
            a[1] = __float_as_uint(Xs[wm + g + 8][ks * 8 + t4    ]);
            a[2] = __float_as_uint(Xs[wm + g    ][ks * 8 + t4 + 4]);
            a[3] = __float_as_uint(Xs[wm + g + 8][ks * 8 + t4 + 4]);
            #pragma unroll
            for (int nt = 0; nt < 8; nt++) {
                uint32_t b0 = __float_as_uint(Ws[ks * 8 + t4    ][nt * 8 + g]);
                uint32_t b1 = __float_as_uint(Ws[ks * 8 + t4 + 4][nt * 8 + g]);
                mma8(acc[nt], a, b0, b1);
            }
        }
        __syncthreads();
    }

    // epilogue -> fp16 (Q pre-scaled; V transposed)
    #pragma unroll
    for (int nt = 0; nt < 8; nt++) {
        const int col = nt * 8 + 2 * t4;
        const float b0 = bias[col], b1 = bias[col + 1];
        const int rowA = m0 + wm + g, rowB = rowA + 8;
        float a0 = acc[nt][0] + b0, a1 = acc[nt][1] + b1;
        float a2 = acc[nt][2] + b0, a3 = acc[nt][3] + b1;
        if (which == 0) {
            *(uint32_t*)(g_q + (size_t)rowA * DK + col) = packh2(a0 * 0.125f, a1 * 0.125f);
            *(uint32_t*)(g_q + (size_t)rowB * DK + col) = packh2(a2 * 0.125f, a3 * 0.125f);
        } else if (which == 1) {
            *(uint32_t*)(g_k + (size_t)rowA * DK + col) = packh2(a0, a1);
            *(uint32_t*)(g_k + (size_t)rowB * DK + col) = packh2(a2, a3);
        } else {
            g_vt[(size_t)(col    ) * MROWS + rowA] = __float2half_rn(a0);
            g_vt[(size_t)(col + 1) * MROWS + rowA] = __float2half_rn(a1);
            g_vt[(size_t)(col    ) * MROWS + rowB] = __float2half_rn(a2);
            g_vt[(size_t)(col + 1) * MROWS + rowB] = __float2half_rn(a3);
        }
    }
}

// ============================================================
// Flash attention, fp16 m16n8k16.
// CTA: 128 thr (4 warps x 16 q-rows = 64 q). KV tiles of 64 keys.
// S C-fragments reused directly as PV A-fragments (no P smem).
// ============================================================
#define FP 88            // smem pitch in halfs (176 B): frag LDS conflict-free
#define FPB 176

__global__ __launch_bounds__(128) void flash_fp16(float* __restrict__ out)
{
    __shared__ __align__(16) __half Ks[64 * FP];   // [key][d]
    __shared__ __align__(16) __half Vs[64 * FP];   // [d][key]

    const int tid  = threadIdx.x;
    const int warp = tid >> 5;
    const int lane = tid & 31;
    const int g    = lane >> 2;
    const int t4   = lane & 3;
    const int b    = blockIdx.y;
    const int q0   = blockIdx.x * 64 + warp * 16;

    // ---- Q fragments (already scaled by 1/8 in projection) ----
    uint32_t q[16];
    {
        const __half* Qg = g_q + (size_t)(b * SEQ + q0) * DK;
        #pragma unroll
        for (int ks = 0; ks < 4; ks++) {
            q[ks * 4 + 0] = *(const uint32_t*)(Qg + (size_t)(g    ) * DK + ks * 16 + 2 * t4    );
            q[ks * 4 + 1] = *(const uint32_t*)(Qg + (size_t)(g + 8) * DK + ks * 16 + 2 * t4    );
            q[ks * 4 + 2] = *(const uint32_t*)(Qg + (size_t)(g    ) * DK + ks * 16 + 2 * t4 + 8);
            q[ks * 4 + 3] = *(const uint32_t*)(Qg + (size_t)(g + 8) * DK + ks * 16 + 2 * t4 + 8);
        }
    }

    float o[8][4];
    #pragma unroll
    for (int nt = 0; nt < 8; nt++)
        #pragma unroll
        for (int j = 0; j < 4; j++) o[nt][j] = 0.f;
    float mA = -INFINITY, mB = -INFINITY, lA = 0.f, lB = 0.f;

    const __half* Kg0 = g_k + (size_t)(b * SEQ) * DK;

    for (int kt = 0; kt < SEQ; kt += 64) {
        __syncthreads();   // previous tile consumed

        // ---- load K[64 keys][64 d] and Vt[64 d][64 keys] (uint4) ----
        {
            const char* Kg = (const char*)(Kg0 + (size_t)kt * DK);
            const __half* Vg = g_vt + (size_t)(b * SEQ + kt);
            #pragma unroll
            for (int it = 0; it < 4; it++) {
                int i = tid + it * 128;        // 512 uint4
                int r = i >> 3, c = i & 7;
                *(uint4*)((char*)Ks + r * FPB + c * 16) =
                    *(const uint4*)(Kg + r * 128 + c * 16);
                *(uint4*)((char*)Vs + r * FPB + c * 16) =
                    *(const uint4*)((const char*)(Vg + (size_t)r * MROWS) + c * 16);
            }
        }
        __syncthreads();

        // ---- S = Q @ K^T  (4 k-chunks of 16) ----
        float s[8][4];
        #pragma unroll
        for (int nt = 0; nt < 8; nt++)
            #pragma unroll
            for (int j = 0; j < 4; j++) s[nt][j] = 0.f;

        #pragma unroll
        for (int ks = 0; ks < 4; ks++) {
            #pragma unroll
            for (int nt = 0; nt < 8; nt++) {
                const char* kb = (const char*)Ks + (nt * 8 + g) * FPB + ks * 32 + t4 * 4;
                uint32_t b0 = *(const uint32_t*)kb;
                uint32_t b1 = *(const uint32_t*)(kb + 16);
                mma16(s[nt], &q[ks * 4], b0, b1);
            }
        }

        // ---- online softmax (rows g / g+8) ----
        float mxA = -INFINITY, mxB = -INFINITY;
        #pragma unroll
        for (int nt = 0; nt < 8; nt++) {
            mxA = fmaxf(mxA, fmaxf(s[nt][0], s[nt][1]));
            mxB = fmaxf(mxB, fmaxf(s[nt][2], s[nt][3]));
        }
        mxA = fmaxf(mxA, __shfl_xor_sync(0xffffffffu, mxA, 1));
        mxA = fmaxf(mxA, __shfl_xor_sync(0xffffffffu, mxA, 2));
        mxB = fmaxf(mxB, __shfl_xor_sync(0xffffffffu, mxB, 1));
        mxB = fmaxf(mxB, __shfl_xor_sync(0xffffffffu, mxB, 2));

        const float mnA = fmaxf(mA, mxA), mnB = fmaxf(mB, mxB);
        const float cA = __expf(mA - mnA), cB = __expf(mB - mnB);

        float sumA = 0.f, sumB = 0.f;
        #pragma unroll
        for (int nt = 0; nt < 8; nt++) {
            s[nt][0] = __expf(s[nt][0] - mnA);
            s[nt][1] = __expf(s[nt][1] - mnA);
            s[nt][2] = __expf(s[nt][2] - mnB);
            s[nt][3] = __expf(s[nt][3] - mnB);
            sumA += s[nt][0] + s[nt][1];
            sumB += s[nt][2] + s[nt][3];
        }
        sumA += __shfl_xor_sync(0xffffffffu, sumA, 1);
        sumA += __shfl_xor_sync(0xffffffffu, sumA, 2);
        sumB += __shfl_xor_sync(0xffffffffu, sumB, 1);
        sumB += __shfl_xor_sync(0xffffffffu, sumB, 2);
        lA = lA * cA + sumA;  mA = mnA;
        lB = lB * cB + sumB;  mB = mnB;

        #pragma unroll
        for (int nt = 0; nt < 8; nt++) {
            o[nt][0] *= cA; o[nt][1] *= cA;
            o[nt][2] *= cB; o[nt][3] *= cB;
        }

        // ---- O += P @ V : S frags ARE the A frags (no smem) ----
        #pragma unroll
        for (int ks = 0; ks < 4; ks++) {
            uint32_t a[4];
            a[0] = packh2(s[2 * ks    ][0], s[2 * ks    ][1]);
            a[1] = packh2(s[2 * ks    ][2], s[2 * ks    ][3]);
            a[2] = packh2(s[2 * ks + 1][0], s[2 * ks + 1][1]);
            a[3] = packh2(s[2 * ks + 1][2], s[2 * ks + 1][3]);
            #pragma unroll
            for (int nt = 0; nt < 8; nt++) {
                const char* vb = (const char*)Vs + (nt * 8 + g) * FPB + ks * 32 + t4 * 4;
                uint32_t b0 = *(const uint32_t*)vb;
                uint32_t b1 = *(const uint32_t*)(vb + 16);
                mma16(o[nt], a, b0, b1);
            }
        }
    }

    // ---- epilogue ----
    const float ilA = 1.f / lA, ilB = 1.f / lB;
    const int rowA = b * SEQ + q0 + g;
    const int rowB = rowA + 8;
    #pragma unroll
    for (int nt = 0; nt < 8; nt++) {
        const int col = nt * 8 + 2 * t4;
        float2 oa = {o[nt][0] * ilA, o[nt][1] * ilA};
        float2 ob = {o[nt][2] * ilB, o[nt][3] * ilB};
        *(float2*)(out + (size_t)rowA * DK + col) = oa;
        *(float2*)(out + (size_t)rowB * DK + col) = ob;
    }
}

// ---------------- launch ----------------
extern "C" void kernel_launch(void* const* d_in, const int* in_sizes, int n_in,
                              void* d_out, int out_size)
{
    const float* input1 = (const float*)d_in[0];
    const float* input2 = (const float*)d_in[1];
    const float* Wq = (const float*)d_in[2];
    const float* bq = (const float*)d_in[3];
    const float* Wk = (const float*)d_in[4];
    const float* bk = (const float*)d_in[5];
    const float* Wv = (const float*)d_in[6];
    const float* bv = (const float*)d_in[7];
    float* out = (float*)d_out;

    (void)in_sizes; (void)n_in; (void)out_size;

    dim3 pgrid(MROWS / 128, 1, 3);
    proj_mma<<<pgrid, 256>>>(input1, input2, Wq, bq, Wk, bk, Wv, bv);

    dim3 fgrid(SEQ / 64, BATCH);
    flash_fp16<<<fgrid, 128>>>(out);
}